// round 4
// baseline (speedup 1.0000x reference)
#include <cuda_runtime.h>

#define NC      6
#define NBINS   36
#define NWARPS  8
#define TPB     256
#define NBLOCKS 1184   // 148 SMs * 8

// Per-block partial confusion matrices, layout [bin][block] for coalesced tail reads.
// Each block overwrites its slot completely -> no zeroing kernel needed.
__device__ unsigned int g_part[NBINS][NBLOCKS];
__device__ unsigned int g_ticket;   // last-block-done counter; reset by last block

__global__ void __launch_bounds__(TPB) kappa_fused_kernel(
    const float* __restrict__ yp,
    const int* __restrict__ yt,     // y_true is int32 (JAX x64-demotion)
    int n,
    float* __restrict__ out)
{
    // Per-THREAD u16 histograms, bin-major: hist[bin][tid].
    // Lane accesses at fixed bin are consecutive addresses -> conflict-free,
    // and different bins across lanes still map to distinct (word,byte) slots.
    __shared__ unsigned short hist[NBINS][TPB];   // 18432 B

    const int tid  = threadIdx.x;
    const int warp = tid >> 5;
    const int lane = tid & 31;

    // Zero our smem (each thread 18 words of the 4608-word array).
    unsigned int* histw = (unsigned int*)hist;
    #pragma unroll
    for (int i = 0; i < (NBINS * TPB / 2) / TPB; i++)
        histw[tid + i * TPB] = 0u;
    __syncthreads();

    const int ngroups = n >> 2;                   // groups of 4 rows
    const float4* yp4 = (const float4*)yp;        // 6 float4 per group (24 floats)
    const int4*   yt4 = (const int4*)yt;          // 1 int4 per group (4 labels)
    const int stride = gridDim.x * blockDim.x;

    for (int g = blockIdx.x * blockDim.x + tid; g < ngroups; g += stride) {
        float4 f0 = yp4[(size_t)g * 6 + 0];
        float4 f1 = yp4[(size_t)g * 6 + 1];
        float4 f2 = yp4[(size_t)g * 6 + 2];
        float4 f3 = yp4[(size_t)g * 6 + 3];
        float4 f4 = yp4[(size_t)g * 6 + 4];
        float4 f5 = yp4[(size_t)g * 6 + 5];
        int4   t4 = yt4[g];

        float v[24];
        v[0]=f0.x;  v[1]=f0.y;  v[2]=f0.z;  v[3]=f0.w;
        v[4]=f1.x;  v[5]=f1.y;  v[6]=f1.z;  v[7]=f1.w;
        v[8]=f2.x;  v[9]=f2.y;  v[10]=f2.z; v[11]=f2.w;
        v[12]=f3.x; v[13]=f3.y; v[14]=f3.z; v[15]=f3.w;
        v[16]=f4.x; v[17]=f4.y; v[18]=f4.z; v[19]=f4.w;
        v[20]=f5.x; v[21]=f5.y; v[22]=f5.z; v[23]=f5.w;

        int tt[4];
        tt[0] = t4.x; tt[1] = t4.y; tt[2] = t4.z; tt[3] = t4.w;

        #pragma unroll
        for (int r = 0; r < 4; r++) {
            const int base = r * 6;
            float bv = v[base];
            int   bi = 0;
            #pragma unroll
            for (int c = 1; c < 6; c++) {
                // strict > keeps FIRST max, matching jnp.argmax tie-break
                if (v[base + c] > bv) { bv = v[base + c]; bi = c; }
            }
            hist[tt[r] * NC + bi][tid]++;    // private column: no race, no atomic
        }
    }

    // Tail rows (n % 4), handled scalar by block 0 (distinct tids -> still race-free).
    if (blockIdx.x == 0 && tid < (n & 3)) {
        const int r = (n & ~3) + tid;
        const float* row = yp + (size_t)r * 6;
        float bv = row[0];
        int   bi = 0;
        #pragma unroll
        for (int c = 1; c < 6; c++) {
            float x = row[c];
            if (x > bv) { bv = x; bi = c; }
        }
        hist[yt[r] * NC + bi][tid]++;
    }

    __syncthreads();

    // Block merge: warp w reduces bins w, w+8, ... (coalesced u16 reads + shuffle).
    for (int b = warp; b < NBINS; b += NWARPS) {
        unsigned int s = 0;
        #pragma unroll
        for (int i = 0; i < TPB / 32; i++)
            s += hist[b][lane + i * 32];
        #pragma unroll
        for (int o = 16; o; o >>= 1)
            s += __shfl_xor_sync(0xffffffffu, s, o);
        if (lane == 0) g_part[b][blockIdx.x] = s;
    }
    __threadfence();   // release partials
    __syncthreads();

    // Last-block-done: final reduce + kappa.
    __shared__ unsigned int s_last;
    __shared__ unsigned int s_conf[NBINS];
    if (tid == 0)
        s_last = (atomicAdd(&g_ticket, 1u) == (unsigned)(gridDim.x - 1)) ? 1u : 0u;
    __syncthreads();
    if (!s_last) return;

    __threadfence();   // acquire: all blocks' partials visible

    if (tid < NBINS) s_conf[tid] = 0u;
    __syncthreads();

    // 252 threads: thread handles bin=tid/7, slots tid%7, tid%7+7, ...
    if (tid < NBINS * 7) {
        const int bin  = tid / 7;
        const int slot = tid % 7;
        volatile const unsigned int* row = &g_part[bin][0];
        unsigned int s = 0;
        for (int b = slot; b < NBLOCKS; b += 7) s += row[b];
        atomicAdd(&s_conf[bin], s);
    }
    __syncthreads();

    if (tid == 0) {
        double conf[NBINS];
        double ht[NC] = {0}, hp[NC] = {0};
        double tot = 0.0;
        #pragma unroll
        for (int i = 0; i < NBINS; i++) {
            conf[i] = (double)s_conf[i];
            tot += conf[i];
        }
        #pragma unroll
        for (int i = 0; i < NC; i++)
            #pragma unroll
            for (int j = 0; j < NC; j++) {
                ht[i] += conf[i * NC + j];
                hp[j] += conf[i * NC + j];
            }
        double num = 0.0, den = 0.0;
        #pragma unroll
        for (int i = 0; i < NC; i++)
            #pragma unroll
            for (int j = 0; j < NC; j++) {
                const double w = (double)((i - j) * (i - j));
                num += w * conf[i * NC + j];
                den += w * ht[i] * hp[j];
            }
        out[0] = (float)(1.0 - (num * tot) / den);
        g_ticket = 0u;   // reset for next graph replay (deterministic)
    }
}

extern "C" void kernel_launch(void* const* d_in, const int* in_sizes, int n_in,
                              void* d_out, int out_size) {
    const float* yp  = (const float*)d_in[0];
    const int*   yt  = (const int*)d_in[1];
    float*       out = (float*)d_out;
    const int n = in_sizes[1];   // number of rows (y_true element count)

    kappa_fused_kernel<<<NBLOCKS, TPB>>>(yp, yt, n, out);
}

// round 5
// speedup vs baseline: 1.4201x; 1.4201x over previous
#include <cuda_runtime.h>

#define NC      6
#define NWARPS  8
#define TPB     256
#define NBLOCKS 1184   // 148 SMs * 8
#define NVALS   13     // ht[6], hp[6], dsum

// Per-block partials, [val][block] for coalesced tail reads. Fully overwritten
// by each block every launch -> no zeroing kernel needed.
__device__ unsigned int g_part[NVALS][NBLOCKS];
__device__ unsigned int g_ticket;   // last-block-done counter; reset by last block

__global__ void __launch_bounds__(TPB) kappa_fused_kernel(
    const float* __restrict__ yp,
    const int* __restrict__ yt,     // y_true is int32 (JAX x64-demotion)
    int n,
    float* __restrict__ out)
{
    const int tid  = threadIdx.x;
    const int warp = tid >> 5;
    const int lane = tid & 31;

    // Register accumulators: packed 6x10-bit histograms + squared-diff sum.
    unsigned long long ht_pack = 0ull;   // count of y_true==c in bits [10c,10c+10)
    unsigned long long hp_pack = 0ull;   // count of argmax==c
    unsigned int dsum = 0u;              // sum (t-p)^2

    const int ngroups = n >> 2;                   // groups of 4 rows
    const float4* yp4 = (const float4*)yp;        // 6 float4 per group (24 floats)
    const int4*   yt4 = (const int4*)yt;          // 1 int4 per group (4 labels)
    const int stride = gridDim.x * blockDim.x;

    for (int g = blockIdx.x * blockDim.x + tid; g < ngroups; g += stride) {
        float4 f0 = yp4[(size_t)g * 6 + 0];
        float4 f1 = yp4[(size_t)g * 6 + 1];
        float4 f2 = yp4[(size_t)g * 6 + 2];
        float4 f3 = yp4[(size_t)g * 6 + 3];
        float4 f4 = yp4[(size_t)g * 6 + 4];
        float4 f5 = yp4[(size_t)g * 6 + 5];
        int4   t4 = yt4[g];

        float v[24];
        v[0]=f0.x;  v[1]=f0.y;  v[2]=f0.z;  v[3]=f0.w;
        v[4]=f1.x;  v[5]=f1.y;  v[6]=f1.z;  v[7]=f1.w;
        v[8]=f2.x;  v[9]=f2.y;  v[10]=f2.z; v[11]=f2.w;
        v[12]=f3.x; v[13]=f3.y; v[14]=f3.z; v[15]=f3.w;
        v[16]=f4.x; v[17]=f4.y; v[18]=f4.z; v[19]=f4.w;
        v[20]=f5.x; v[21]=f5.y; v[22]=f5.z; v[23]=f5.w;

        int tt[4];
        tt[0] = t4.x; tt[1] = t4.y; tt[2] = t4.z; tt[3] = t4.w;

        #pragma unroll
        for (int r = 0; r < 4; r++) {
            const int base = r * 6;
            float bv = v[base];
            int   bi = 0;
            #pragma unroll
            for (int c = 1; c < 6; c++) {
                // strict > keeps FIRST max, matching jnp.argmax tie-break
                if (v[base + c] > bv) { bv = v[base + c]; bi = c; }
            }
            const int t = tt[r];
            const int d = t - bi;
            dsum    += (unsigned)(d * d);
            ht_pack += 1ull << (t  * 10);
            hp_pack += 1ull << (bi * 10);
        }
    }

    // Tail rows (n % 4): block 0, distinct threads, into their own registers.
    if (blockIdx.x == 0 && tid < (n & 3)) {
        const int r = (n & ~3) + tid;
        const float* row = yp + (size_t)r * 6;
        float bv = row[0];
        int   bi = 0;
        #pragma unroll
        for (int c = 1; c < 6; c++) {
            float x = row[c];
            if (x > bv) { bv = x; bi = c; }
        }
        const int t = yt[r];
        const int d = t - bi;
        dsum    += (unsigned)(d * d);
        ht_pack += 1ull << (t  * 10);
        hp_pack += 1ull << (bi * 10);
    }

    // Unpack to 13 u32 and warp shuffle-reduce.
    unsigned int vals[NVALS];
    #pragma unroll
    for (int c = 0; c < NC; c++) {
        vals[c]      = (unsigned int)((ht_pack >> (c * 10)) & 0x3FFu);
        vals[NC + c] = (unsigned int)((hp_pack >> (c * 10)) & 0x3FFu);
    }
    vals[12] = dsum;

    #pragma unroll
    for (int k = 0; k < NVALS; k++) {
        unsigned int s = vals[k];
        #pragma unroll
        for (int o = 16; o; o >>= 1)
            s += __shfl_xor_sync(0xffffffffu, s, o);
        vals[k] = s;
    }

    // Block merge via shared: lane 0 of each warp deposits its 13 sums.
    __shared__ unsigned int s_w[NWARPS][NVALS];
    if (lane == 0) {
        #pragma unroll
        for (int k = 0; k < NVALS; k++) s_w[warp][k] = vals[k];
    }
    __syncthreads();
    if (tid < NVALS) {
        unsigned int s = 0;
        #pragma unroll
        for (int w = 0; w < NWARPS; w++) s += s_w[w][tid];
        g_part[tid][blockIdx.x] = s;
    }
    __threadfence();   // release partials
    __syncthreads();

    // Last-block-done: final reduce + kappa.
    __shared__ unsigned int s_last;
    __shared__ unsigned int s_acc[NVALS];
    if (tid == 0)
        s_last = (atomicAdd(&g_ticket, 1u) == (unsigned)(gridDim.x - 1)) ? 1u : 0u;
    __syncthreads();
    if (!s_last) return;

    __threadfence();   // acquire: all blocks' partials visible

    if (tid < NVALS) s_acc[tid] = 0u;
    __syncthreads();

    // 13 values x 19 slices = 247 active threads; ~62 L2 loads each.
    {
        const int k     = tid % NVALS;
        const int slice = tid / NVALS;
        if (slice < 19) {
            volatile const unsigned int* row = &g_part[k][0];
            unsigned int s = 0;
            for (int b = slice; b < NBLOCKS; b += 19) s += row[b];
            atomicAdd(&s_acc[k], s);
        }
    }
    __syncthreads();

    if (tid == 0) {
        double ht[NC], hp[NC];
        #pragma unroll
        for (int c = 0; c < NC; c++) {
            ht[c] = (double)s_acc[c];
            hp[c] = (double)s_acc[NC + c];
        }
        const double num = (double)s_acc[12];   // sum W*conf (unnormalized)
        double den = 0.0;
        #pragma unroll
        for (int i = 0; i < NC; i++)
            #pragma unroll
            for (int j = 0; j < NC; j++)
                den += (double)((i - j) * (i - j)) * ht[i] * hp[j];
        const double N = (double)n;
        out[0] = (float)(1.0 - (num * N) / den);
        g_ticket = 0u;   // reset for next graph replay (deterministic)
    }
}

extern "C" void kernel_launch(void* const* d_in, const int* in_sizes, int n_in,
                              void* d_out, int out_size) {
    const float* yp  = (const float*)d_in[0];
    const int*   yt  = (const int*)d_in[1];
    float*       out = (float*)d_out;
    const int n = in_sizes[1];   // number of rows (y_true element count)

    kappa_fused_kernel<<<NBLOCKS, TPB>>>(yp, yt, n, out);
}

// round 6
// speedup vs baseline: 1.4335x; 1.0094x over previous
#include <cuda_runtime.h>

#define NC      6
#define NWARPS  8
#define TPB     256
#define NBLOCKS 1184   // 148 SMs * 8
#define NVALS   13     // ht[6], hp[6], dsum

// Per-block partials, [val][block] for coalesced tail reads. Fully overwritten
// by each block every launch -> no zeroing kernel needed.
__device__ unsigned int g_part[NVALS][NBLOCKS];
__device__ unsigned int g_ticket;   // last-block-done counter; reset by last block

__global__ void __launch_bounds__(TPB) kappa_fused_kernel(
    const float* __restrict__ yp,
    const int* __restrict__ yt,     // y_true is int32 (JAX x64-demotion)
    int n,
    float* __restrict__ out)
{
    const int tid  = threadIdx.x;
    const int warp = tid >> 5;
    const int lane = tid & 31;

    // Register accumulators: packed 6x10-bit histograms + squared-diff sum.
    unsigned long long ht_pack = 0ull;   // count of y_true==c in bits [10c,10c+10)
    unsigned long long hp_pack = 0ull;   // count of argmax==c
    unsigned int dsum = 0u;              // sum (t-p)^2

    const int ngroups = n >> 1;                   // groups of 2 rows
    const float4* yp4 = (const float4*)yp;        // 3 float4 per group (12 floats)
    const int2*   yt2 = (const int2*)yt;          // 1 int2 per group (2 labels)
    const int stride = gridDim.x * blockDim.x;

    for (int g = blockIdx.x * blockDim.x + tid; g < ngroups; g += stride) {
        float4 f0 = yp4[(size_t)g * 3 + 0];
        float4 f1 = yp4[(size_t)g * 3 + 1];
        float4 f2 = yp4[(size_t)g * 3 + 2];
        int2   t2 = yt2[g];

        float v[12];
        v[0]=f0.x; v[1]=f0.y; v[2]=f0.z;  v[3]=f0.w;
        v[4]=f1.x; v[5]=f1.y; v[6]=f1.z;  v[7]=f1.w;
        v[8]=f2.x; v[9]=f2.y; v[10]=f2.z; v[11]=f2.w;

        int tt[2];
        tt[0] = t2.x; tt[1] = t2.y;

        #pragma unroll
        for (int r = 0; r < 2; r++) {
            const int base = r * 6;
            float bv = v[base];
            int   bi = 0;
            #pragma unroll
            for (int c = 1; c < 6; c++) {
                // strict > keeps FIRST max, matching jnp.argmax tie-break
                if (v[base + c] > bv) { bv = v[base + c]; bi = c; }
            }
            const int t = tt[r];
            const int d = t - bi;
            dsum    += (unsigned)(d * d);
            ht_pack += 1ull << (t  * 10);
            hp_pack += 1ull << (bi * 10);
        }
    }

    // Tail row (n odd): block 0, thread 0.
    if (blockIdx.x == 0 && tid == 0 && (n & 1)) {
        const int r = n - 1;
        const float* row = yp + (size_t)r * 6;
        float bv = row[0];
        int   bi = 0;
        #pragma unroll
        for (int c = 1; c < 6; c++) {
            float x = row[c];
            if (x > bv) { bv = x; bi = c; }
        }
        const int t = yt[r];
        const int d = t - bi;
        dsum    += (unsigned)(d * d);
        ht_pack += 1ull << (t  * 10);
        hp_pack += 1ull << (bi * 10);
    }

    // Unpack to 13 u32 and warp shuffle-reduce.
    unsigned int vals[NVALS];
    #pragma unroll
    for (int c = 0; c < NC; c++) {
        vals[c]      = (unsigned int)((ht_pack >> (c * 10)) & 0x3FFu);
        vals[NC + c] = (unsigned int)((hp_pack >> (c * 10)) & 0x3FFu);
    }
    vals[12] = dsum;

    #pragma unroll
    for (int k = 0; k < NVALS; k++) {
        unsigned int s = vals[k];
        #pragma unroll
        for (int o = 16; o; o >>= 1)
            s += __shfl_xor_sync(0xffffffffu, s, o);
        vals[k] = s;
    }

    // Block merge via shared: lane 0 of each warp deposits its 13 sums.
    __shared__ unsigned int s_w[NWARPS][NVALS];
    if (lane == 0) {
        #pragma unroll
        for (int k = 0; k < NVALS; k++) s_w[warp][k] = vals[k];
    }
    __syncthreads();
    if (tid < NVALS) {
        unsigned int s = 0;
        #pragma unroll
        for (int w = 0; w < NWARPS; w++) s += s_w[w][tid];
        g_part[tid][blockIdx.x] = s;
    }
    __threadfence();   // release partials
    __syncthreads();

    // Last-block-done: final reduce + kappa.
    __shared__ unsigned int s_last;
    __shared__ unsigned int s_acc[NVALS];
    if (tid == 0)
        s_last = (atomicAdd(&g_ticket, 1u) == (unsigned)(gridDim.x - 1)) ? 1u : 0u;
    __syncthreads();
    if (!s_last) return;

    __threadfence();   // acquire: all blocks' partials visible

    if (tid < NVALS) s_acc[tid] = 0u;
    __syncthreads();

    // 13 values x 19 slices = 247 active threads; ~62 L2 loads each.
    {
        const int k     = tid % NVALS;
        const int slice = tid / NVALS;
        if (slice < 19) {
            volatile const unsigned int* row = &g_part[k][0];
            unsigned int s = 0;
            for (int b = slice; b < NBLOCKS; b += 19) s += row[b];
            atomicAdd(&s_acc[k], s);
        }
    }
    __syncthreads();

    if (tid == 0) {
        double ht[NC], hp[NC];
        #pragma unroll
        for (int c = 0; c < NC; c++) {
            ht[c] = (double)s_acc[c];
            hp[c] = (double)s_acc[NC + c];
        }
        const double num = (double)s_acc[12];   // sum W*conf (unnormalized)
        double den = 0.0;
        #pragma unroll
        for (int i = 0; i < NC; i++)
            #pragma unroll
            for (int j = 0; j < NC; j++)
                den += (double)((i - j) * (i - j)) * ht[i] * hp[j];
        const double N = (double)n;
        out[0] = (float)(1.0 - (num * N) / den);
        g_ticket = 0u;   // reset for next graph replay (deterministic)
    }
}

extern "C" void kernel_launch(void* const* d_in, const int* in_sizes, int n_in,
                              void* d_out, int out_size) {
    const float* yp  = (const float*)d_in[0];
    const int*   yt  = (const int*)d_in[1];
    float*       out = (float*)d_out;
    const int n = in_sizes[1];   // number of rows (y_true element count)

    kappa_fused_kernel<<<NBLOCKS, TPB>>>(yp, yt, n, out);
}